// round 16
// baseline (speedup 1.0000x reference)
#include <cuda_runtime.h>
#include <cuda_fp16.h>
#include <mma.h>
using namespace nvcuda;

#define D 128
#define MAXN 50176
#define MAXE 524288
#define SCAN_B 1024
#define PIPE 4

typedef unsigned long long u64;
typedef unsigned int u32;

// ---- tc_gemm smem layout (bytes from dynamic smem base) ----
#define BN0_OFF 0
#define BN1_OFF 512
#define ST0_OFF 1024
#define ST1_OFF 1536
#define TILE_OFF 2048
#define LDA 72
#define LDB 136
#define AH_OFF (TILE_OFF)
#define BH_OFF (AH_OFF + 128 * LDA * 2)
#define BL_OFF (BH_OFF + 64 * LDB * 2)
#define TCSMEM 69632

// cp.async helpers
__device__ __forceinline__ void cpa16_stream(u32 dst, const void* src, u64 pol) {
    asm volatile("cp.async.cg.shared.global.L2::cache_hint [%0], [%1], 16, %2;"
                 :: "r"(dst), "l"(src), "l"(pol));
}
#define CP_COMMIT() asm volatile("cp.async.commit_group;" ::: "memory")
#define CP_WAIT(n)  asm volatile("cp.async.wait_group %0;" :: "n"(n) : "memory")

__device__ __forceinline__ u32 smem_u32(const void* p) {
    u32 a;
    asm("{ .reg .u64 t; cvta.to.shared.u64 t, %1; cvt.u32.u64 %0, t; }" : "=r"(a) : "l"(p));
    return a;
}

// ---- device scratch ----
__device__ float g_agg[MAXN * D];
__device__ float g_h[MAXN * D];
__device__ float g_x1[MAXN * D];
__device__ float g_sum[D];
__device__ float g_sq[D];
__device__ int g_cnt[MAXN];      // zero at load; re-zeroed by scatter each launch
__device__ int g_rowptr[MAXN];
__device__ int g_fill[MAXN];
__device__ int g_perm[MAXE];
__device__ int g_se[MAXE];
__device__ int g_bsum[64];
__device__ int g_ready;          // zero at load; re-zeroed by scatter each launch

// ================= CSR build (3 kernels) =================
__global__ void hist_kernel(const int* __restrict__ ei, int* __restrict__ cnt, int E) {
    int i = blockIdx.x * blockDim.x + threadIdx.x;
    if (i < E) atomicAdd(&cnt[__ldg(ei + E + i)], 1);
}

// single-pass scan: local block scan + grid quiescence on atomic counter.
// All blocks (<=49) are co-resident, so the spin cannot deadlock.
__global__ __launch_bounds__(SCAN_B) void scan_kernel(
    const int* __restrict__ cnt, int* __restrict__ rowptr, int* __restrict__ fill,
    int* __restrict__ bsum, int* __restrict__ ready, int n)
{
    __shared__ int sh[SCAN_B];
    __shared__ int boff_s;
    int t = threadIdx.x;
    int b = blockIdx.x;
    int i = b * SCAN_B + t;
    int v = (i < n) ? cnt[i] : 0;
    sh[t] = v;
    __syncthreads();
#pragma unroll
    for (int off = 1; off < SCAN_B; off <<= 1) {
        int add = (t >= off) ? sh[t - off] : 0;
        __syncthreads();
        sh[t] += add;
        __syncthreads();
    }
    if (t == SCAN_B - 1) {
        bsum[b] = sh[t];
        __threadfence();
        atomicAdd(ready, 1);
    }
    if (t == 0) {
        while (atomicAdd(ready, 0) < gridDim.x) { }
        __threadfence();
        int acc = 0;
        for (int k = 0; k < b; k++) acc += bsum[k];
        boff_s = acc;
    }
    __syncthreads();
    if (i < n) {
        int r = sh[t] - v + boff_s;
        rowptr[i] = r;
        fill[i] = r;
    }
}

__global__ void scatter_kernel(const int* __restrict__ ei, int* __restrict__ fill,
                               int* __restrict__ perm, int* __restrict__ se,
                               int* __restrict__ cnt, int* __restrict__ ready,
                               int E, int N) {
    int e = blockIdx.x * blockDim.x + threadIdx.x;
    if (e < N) cnt[e] = 0;
    if (e == 0) *ready = 0;
    if (e < E) {
        int s = __ldg(ei + e);
        int d = __ldg(ei + E + e);
        int idx = atomicAdd(&fill[d], 1);
        perm[idx] = e;
        se[idx] = s;
    }
}

// ========== aggregate: ea via cp.async (evict-first), x direct LDG w/ depth-2 prefetch ==========
__global__ __launch_bounds__(256) void agg_kernel(
    const float* __restrict__ x, const float* __restrict__ ea,
    const int* __restrict__ rowptr, const int* __restrict__ rowend,
    const int* __restrict__ perm, const int* __restrict__ se,
    float* __restrict__ agg, float* __restrict__ ssum, float* __restrict__ ssq, int N)
{
    __shared__ float4 buf[8][PIPE][32];   // ea only: 16 KB
    if (blockIdx.x == 0 && threadIdx.x < D) {
        ssum[threadIdx.x] = 0.f;
        ssq[threadIdx.x] = 0.f;
    }
    int w = threadIdx.x >> 5;
    int lane = threadIdx.x & 31;
    int v = blockIdx.x * 8 + w;
    if (v >= N) return;
    u64 pol;
    asm("createpolicy.fractional.L2::evict_first.b64 %0, 1.0;" : "=l"(pol));
    int j = __ldg(rowptr + v);
    int end = __ldg(rowend + v);
    int deg = end - j;
    const float4* x4 = (const float4*)x;
    const float4* ea4 = (const float4*)ea;
    float4 acc = __ldg(x4 + (size_t)v * 32 + lane);
    u32 bx = smem_u32(&buf[w][0][lane]);   // slot stride = 512 B

    // prologue: ea pipeline (always commit PIPE groups for exact accounting)
#pragma unroll
    for (int p = 0; p < PIPE; p++) {
        if (p < deg) {
            int e = __ldg(perm + j + p);
            cpa16_stream(bx + p * 512, ea4 + (size_t)e * 32 + lane, pol);
        }
        CP_COMMIT();
    }
    // x prefetch depth 2 (L2-resident gather, direct to registers)
    float4 xa = make_float4(0.f, 0.f, 0.f, 0.f);
    float4 xb = make_float4(0.f, 0.f, 0.f, 0.f);
    if (deg > 0) xa = __ldg(x4 + (size_t)__ldg(se + j) * 32 + lane);
    if (deg > 1) xb = __ldg(x4 + (size_t)__ldg(se + j + 1) * 32 + lane);

    int slot = 0;
    for (int i = 0; i < deg; i++) {
        int nj = j + i + PIPE;
        bool isu = (nj < end);                 // warp-uniform
        int e = 0;
        if (isu) e = __ldg(perm + nj);
        float4 xn = make_float4(0.f, 0.f, 0.f, 0.f);
        if (i + 2 < deg)                        // warp-uniform
            xn = __ldg(x4 + (size_t)__ldg(se + j + i + 2) * 32 + lane);
        CP_WAIT(PIPE - 1);                      // group i complete -> ea slot ready
        float4 ev = buf[w][slot][lane];
        if (isu) cpa16_stream(bx + slot * 512, ea4 + (size_t)e * 32 + lane, pol);
        CP_COMMIT();
        acc.x += fmaxf(xa.x + ev.x, 0.f);
        acc.y += fmaxf(xa.y + ev.y, 0.f);
        acc.z += fmaxf(xa.z + ev.z, 0.f);
        acc.w += fmaxf(xa.w + ev.w, 0.f);
        xa = xb;
        xb = xn;
        slot = (slot + 1) & (PIPE - 1);
    }
    asm volatile("cp.async.wait_all;" ::: "memory");
    ((float4*)agg)[(size_t)v * 32 + lane] = acc;
}

// ================= wmma fp16 2-pass GEMM (R15 winner, unchanged) =================
template<int MODE>
__global__ __launch_bounds__(256)
void tc_gemm_kernel(const float* __restrict__ A, const float* __restrict__ W,
                    const float* __restrict__ bias,
                    const float* __restrict__ gamma, const float* __restrict__ beta,
                    float invN,
                    float* __restrict__ out,
                    float* __restrict__ ssum, float* __restrict__ ssq, int M)
{
    extern __shared__ char sm[];
    int tid = threadIdx.x;
    int wid = tid >> 5;
    int lane = tid & 31;
    int row_base = blockIdx.x * 128;

    float* sc_s = (float*)(sm + BN0_OFF);
    float* sh_s = (float*)(sm + BN1_OFF);
    float* st0  = (float*)(sm + ST0_OFF);
    float* st1  = (float*)(sm + ST1_OFF);
    __half* Ah = (__half*)(sm + AH_OFF);
    __half* Bh = (__half*)(sm + BH_OFF);
    __half* Bl = (__half*)(sm + BL_OFF);

    if (tid < D) {
        if (MODE == 1) {
            float m = __ldg(ssum + tid) * invN;
            float var = fmaf(__ldg(ssq + tid), invN, -m * m);
            float r = rsqrtf(var + 1e-5f);
            float sc = r * __ldg(gamma + tid);
            sc_s[tid] = sc;
            sh_s[tid] = fmaf(-m, sc, __ldg(beta + tid));
        } else {
            st0[tid] = 0.f;
            st1[tid] = 0.f;
        }
    }

    wmma::fragment<wmma::accumulator, 16, 16, 16, float> acc[8];
#pragma unroll
    for (int nt = 0; nt < 8; nt++) wmma::fill_fragment(acc[nt], 0.f);

    const float4* A4 = (const float4*)A;
    const float4* W4 = (const float4*)W;

    for (int hh = 0; hh < 2; hh++) {
        int kb = hh * 64;
        __syncthreads();
        // ---- stage A half [128 x 64] as fp16 ----
#pragma unroll
        for (int it = 0; it < 8; it++) {
            int idx = it * 256 + tid;
            int row = idx >> 4;
            int c4  = idx & 15;
            int grow = row_base + row;
            float4 a = make_float4(0.f, 0.f, 0.f, 0.f);
            if (grow < M) {
                a = __ldg(A4 + (size_t)grow * 32 + (kb >> 2) + c4);
                if (MODE == 1) {
                    int gc = kb + c4 * 4;
                    a.x = fmaxf(fmaf(a.x, sc_s[gc + 0], sh_s[gc + 0]), 0.f);
                    a.y = fmaxf(fmaf(a.y, sc_s[gc + 1], sh_s[gc + 1]), 0.f);
                    a.z = fmaxf(fmaf(a.z, sc_s[gc + 2], sh_s[gc + 2]), 0.f);
                    a.w = fmaxf(fmaf(a.w, sc_s[gc + 3], sh_s[gc + 3]), 0.f);
                }
            }
            __half2 p0 = __floats2half2_rn(a.x, a.y);
            __half2 p1 = __floats2half2_rn(a.z, a.w);
            int off = row * LDA + c4 * 4;
            *(uint2*)(Ah + off) = make_uint2(*(u32*)&p0, *(u32*)&p1);
        }
        // ---- stage B = W half [64 x 128] as fp16 hi/lo ----
#pragma unroll
        for (int it = 0; it < 8; it++) {
            int idx = it * 256 + tid;
            int k  = idx >> 5;
            int n4 = idx & 31;
            float4 w = __ldg(W4 + (size_t)(kb + k) * 32 + n4);
            float v[4] = {w.x, w.y, w.z, w.w};
            unsigned short h[4], l[4];
#pragma unroll
            for (int e = 0; e < 4; e++) {
                __half hb = __float2half_rn(v[e]);
                float hf = __half2float(hb);
                __half lb = __float2half_rn(v[e] - hf);
                h[e] = *reinterpret_cast<unsigned short*>(&hb);
                l[e] = *reinterpret_cast<unsigned short*>(&lb);
            }
            int off = k * LDB + n4 * 4;
            *(uint2*)(Bh + off) = make_uint2((u32)h[0] | ((u32)h[1] << 16),
                                             (u32)h[2] | ((u32)h[3] << 16));
            *(uint2*)(Bl + off) = make_uint2((u32)l[0] | ((u32)l[1] << 16),
                                             (u32)l[2] | ((u32)l[3] << 16));
        }
        __syncthreads();
        // ---- mma: each warp = 16 rows x 128 cols, 2-pass ----
        int wrow = wid * 16;
        wmma::fragment<wmma::matrix_a, 16, 16, 16, __half, wmma::row_major> fah;
        wmma::fragment<wmma::matrix_b, 16, 16, 16, __half, wmma::row_major> fbh, fbl;
#pragma unroll
        for (int kc = 0; kc < 4; kc++) {
            wmma::load_matrix_sync(fah, Ah + wrow * LDA + kc * 16, LDA);
#pragma unroll
            for (int nt = 0; nt < 8; nt++) {
                wmma::load_matrix_sync(fbh, Bh + (kc * 16) * LDB + nt * 16, LDB);
                wmma::load_matrix_sync(fbl, Bl + (kc * 16) * LDB + nt * 16, LDB);
                wmma::mma_sync(acc[nt], fah, fbh, acc[nt]);
                wmma::mma_sync(acc[nt], fah, fbl, acc[nt]);
            }
        }
    }
    __syncthreads();   // all tile reads done; reuse tile smem for C staging

    // ---- epilogue ----
    float* Cw = (float*)(sm + TILE_OFF) + wid * 16 * 132;
#pragma unroll
    for (int nt = 0; nt < 8; nt++)
        wmma::store_matrix_sync(Cw + nt * 16, acc[nt], 132, wmma::mem_row_major);
    __syncwarp();

    float bv[4];
#pragma unroll
    for (int e = 0; e < 4; e++) bv[e] = __ldg(bias + lane * 4 + e);
    float cs[4] = {0.f, 0.f, 0.f, 0.f}, cq[4] = {0.f, 0.f, 0.f, 0.f};
#pragma unroll
    for (int i = 0; i < 16; i++) {
        int row = row_base + wid * 16 + i;
        if (row < M) {
            float4 o = *(float4*)(Cw + i * 132 + lane * 4);
            o.x += bv[0]; o.y += bv[1]; o.z += bv[2]; o.w += bv[3];
            if (MODE == 1) {
                o.x = fmaxf(o.x, 0.f); o.y = fmaxf(o.y, 0.f);
                o.z = fmaxf(o.z, 0.f); o.w = fmaxf(o.w, 0.f);
            }
            *(float4*)(out + (size_t)row * D + lane * 4) = o;
            if (MODE == 0) {
                cs[0] += o.x; cq[0] += o.x * o.x;
                cs[1] += o.y; cq[1] += o.y * o.y;
                cs[2] += o.z; cq[2] += o.z * o.z;
                cs[3] += o.w; cq[3] += o.w * o.w;
            }
        }
    }
    if (MODE == 0) {
#pragma unroll
        for (int e = 0; e < 4; e++) {
            atomicAdd(&st0[lane * 4 + e], cs[e]);
            atomicAdd(&st1[lane * 4 + e], cq[e]);
        }
        __syncthreads();
        if (tid < D) {
            atomicAdd(&ssum[tid], st0[tid]);
            atomicAdd(&ssq[tid], st1[tid]);
        }
    }
}

extern "C" void kernel_launch(void* const* d_in, const int* in_sizes, int n_in,
                              void* d_out, int out_size) {
    const float* x     = (const float*)d_in[0];
    const int*   ei    = (const int*)d_in[1];
    const float* ea    = (const float*)d_in[2];
    const float* W1    = (const float*)d_in[3];
    const float* b1    = (const float*)d_in[4];
    const float* gamma = (const float*)d_in[5];
    const float* beta  = (const float*)d_in[6];
    const float* W2    = (const float*)d_in[7];
    const float* b2    = (const float*)d_in[8];

    int M = in_sizes[0] / D;
    int E = in_sizes[2] / D;
    int L = in_sizes[3] / (D * D);
    float invN = 1.0f / (float)M;

    float *p_agg, *p_h, *p_x1, *p_sum, *p_sq;
    int *p_cnt, *p_rowptr, *p_fill, *p_perm, *p_se, *p_bsum, *p_ready;
    cudaGetSymbolAddress((void**)&p_agg,   g_agg);
    cudaGetSymbolAddress((void**)&p_h,     g_h);
    cudaGetSymbolAddress((void**)&p_x1,    g_x1);
    cudaGetSymbolAddress((void**)&p_sum,   g_sum);
    cudaGetSymbolAddress((void**)&p_sq,    g_sq);
    cudaGetSymbolAddress((void**)&p_cnt,    g_cnt);
    cudaGetSymbolAddress((void**)&p_rowptr, g_rowptr);
    cudaGetSymbolAddress((void**)&p_fill,   g_fill);
    cudaGetSymbolAddress((void**)&p_perm,   g_perm);
    cudaGetSymbolAddress((void**)&p_se,     g_se);
    cudaGetSymbolAddress((void**)&p_bsum,   g_bsum);
    cudaGetSymbolAddress((void**)&p_ready,  g_ready);

    cudaFuncSetAttribute(tc_gemm_kernel<0>, cudaFuncAttributeMaxDynamicSharedMemorySize, TCSMEM);
    cudaFuncSetAttribute(tc_gemm_kernel<1>, cudaFuncAttributeMaxDynamicSharedMemorySize, TCSMEM);

    int gemm_blocks = (M + 127) / 128;
    int eb = (E + 255) / 256;
    int nbscan = (M + SCAN_B - 1) / SCAN_B;
    int agg_blocks = (M + 7) / 8;

    // ---- build CSR once: 3 launches (hist, scan, scatter) ----
    hist_kernel<<<eb, 256>>>(ei, p_cnt, E);
    scan_kernel<<<nbscan, SCAN_B>>>(p_cnt, p_rowptr, p_fill, p_bsum, p_ready, M);
    scatter_kernel<<<eb, 256>>>(ei, p_fill, p_perm, p_se, p_cnt, p_ready, E, M);

    for (int l = 0; l < L; l++) {
        const float* xin = (l == 0) ? x : p_x1;
        float* xout = (l == L - 1) ? (float*)d_out : p_x1;

        agg_kernel<<<agg_blocks, 256>>>(xin, ea, p_rowptr, p_fill, p_perm, p_se,
                                        p_agg, p_sum, p_sq, M);
        tc_gemm_kernel<0><<<gemm_blocks, 256, TCSMEM>>>(p_agg,
            W1 + (size_t)l * D * D, b1 + (size_t)l * D,
            nullptr, nullptr, 0.f, p_h, p_sum, p_sq, M);
        tc_gemm_kernel<1><<<gemm_blocks, 256, TCSMEM>>>(p_h,
            W2 + (size_t)l * D * D, b2 + (size_t)l * D,
            gamma + (size_t)l * D, beta + (size_t)l * D, invN,
            xout, p_sum, p_sq, M);
    }
}